// round 6
// baseline (speedup 1.0000x reference)
#include <cuda_runtime.h>
#include <cstdint>

// YOLOv1 loss: pred [4096,14,14,30] fp32, target same, output scalar fp32.
// R6: warp-private cp.async.bulk rings. 8 warps/block, each warp owns a
// 3-stage ring (32 cells = 3840B/array per chunk) with private mbarriers.
// NO block-wide sync in the hot loop: 8 independently-phased DMA streams/SM.

#define NBATCH     4096
#define NCH        30
#define NCELLS     (NBATCH * 14 * 14)       // 802816
#define CH_CELLS   32                       // cells per warp-chunk
#define NCHUNK     (NCELLS / CH_CELLS)      // 25088 exact
#define NWARP      8
#define BLOCK      (NWARP * 32)             // 256
#define NSTAGE     3
#define ARR_B      (CH_CELLS * NCH * 4)     // 3840 B per array per chunk
#define STAGE_B    (2 * ARR_B)              // 7680 B
#define STAGE_F    (STAGE_B / 4)            // 1920 floats
#define WARP_B     (NSTAGE * STAGE_B)       // 23040 B per warp
#define WARP_F     (WARP_B / 4)             // 5760 floats
#define SMEM_DYN   (NWARP * WARP_B)         // 184320 B
#define GRID_N     148
#define TOT_WARPS  (GRID_N * NWARP)         // 1184

__global__ void yolo_zero_out(float* out) {
    if (threadIdx.x == 0) out[0] = 0.0f;
}

__device__ __forceinline__ void mbar_init(uint32_t mbar, uint32_t count) {
    asm volatile("mbarrier.init.shared.b64 [%0], %1;"
                 :: "r"(mbar), "r"(count) : "memory");
}
__device__ __forceinline__ void mbar_expect_tx(uint32_t mbar, uint32_t bytes) {
    asm volatile("mbarrier.arrive.expect_tx.shared.b64 _, [%0], %1;"
                 :: "r"(mbar), "r"(bytes) : "memory");
}
__device__ __forceinline__ void bulk_g2s(uint32_t dst, const void* src,
                                         uint32_t bytes, uint32_t mbar) {
    asm volatile(
        "cp.async.bulk.shared::cluster.global.mbarrier::complete_tx::bytes "
        "[%0], [%1], %2, [%3];"
        :: "r"(dst), "l"(src), "r"(bytes), "r"(mbar) : "memory");
}
__device__ __forceinline__ void mbar_wait(uint32_t mbar, uint32_t parity) {
    asm volatile(
        "{\n\t"
        ".reg .pred P;\n\t"
        "LW%=:\n\t"
        "mbarrier.try_wait.parity.acquire.cta.shared::cta.b64 P, [%0], %1, 0x989680;\n\t"
        "@P bra LD%=;\n\t"
        "bra LW%=;\n\t"
        "LD%=:\n\t"
        "}"
        :: "r"(mbar), "r"(parity) : "memory");
}

extern __shared__ float dynbuf[];

__global__ __launch_bounds__(BLOCK)
void yolo_loss_kernel(const float* __restrict__ pred,
                      const float* __restrict__ tgt,
                      float* __restrict__ out)
{
    __shared__ uint64_t mbar_s[NWARP][NSTAGE];
    __shared__ float wsum[NWARP];

    const int wid  = threadIdx.x >> 5;
    const int lane = threadIdx.x & 31;

    const uint32_t mbar0 = (uint32_t)__cvta_generic_to_shared(&mbar_s[0][0]);
    const uint32_t mwarp = mbar0 + (uint32_t)wid * (NSTAGE * 8u);
    const uint32_t sbase = (uint32_t)__cvta_generic_to_shared(dynbuf)
                         + (uint32_t)wid * WARP_B;
    float* const fwarp = dynbuf + wid * WARP_F;

    if (threadIdx.x == 0) {
        #pragma unroll
        for (int w = 0; w < NWARP; w++)
            #pragma unroll
            for (int s = 0; s < NSTAGE; s++)
                mbar_init(mbar0 + (w * NSTAGE + s) * 8u, 1);
    }
    __syncthreads();   // barriers visible to all warps (only sync before tail)

    const int gw = blockIdx.x * NWARP + wid;            // global warp id
    const int n  = (NCHUNK - gw + TOT_WARPS - 1) / TOT_WARPS;  // 21 or 22

    // issue chunk k of this warp into stage k%NSTAGE (lane 0 only)
    auto issue = [&](int k) {
        const int chunk = gw + k * TOT_WARPS;
        const int s = k % NSTAGE;
        const uint32_t mb  = mwarp + 8u * s;
        const uint32_t dst = sbase + (uint32_t)s * STAGE_B;
        mbar_expect_tx(mb, STAGE_B);
        bulk_g2s(dst,         pred + (size_t)chunk * (CH_CELLS * NCH), ARR_B, mb);
        bulk_g2s(dst + ARR_B, tgt  + (size_t)chunk * (CH_CELLS * NCH), ARR_B, mb);
    };

    if (lane == 0) {            // n >= 21 always, prologue depth 2 safe
        issue(0);
        issue(1);
    }

    const float invS = 1.0f / 14.0f;
    float acc = 0.0f;

    for (int k = 0; k < n; k++) {
        if (lane == 0 && (k + 2) < n) issue(k + 2);

        const int s = k % NSTAGE;
        mbar_wait(mwarp + 8u * s, (uint32_t)((k / NSTAGE) & 1));

        {
            const float* p = fwarp + s * STAGE_F + lane * NCH;
            const float* t = p + (ARR_B / 4);

            // target box 0 (boxes are tiled identical in target)
            const float t0x = t[0], t0y = t[1], t0w = t[2], t0h = t[3];
            const float tobj = t[4];
            const float of = (tobj > 0.0f) ? 1.0f : 0.0f;

            const float tcx = t0x * invS, tcy = t0y * invS;
            const float thw = 0.5f * t0w, thh = 0.5f * t0h;
            const float tx0 = tcx - thw, tx1 = tcx + thw;
            const float ty0 = tcy - thh, ty1 = tcy + thh;
            const float area_t = t0w * t0h;

            float iou[2], px[2], py[2], pw[2], ph[2], pc[2];
            #pragma unroll
            for (int b = 0; b < 2; b++) {
                px[b] = p[5*b + 0]; py[b] = p[5*b + 1];
                pw[b] = p[5*b + 2]; ph[b] = p[5*b + 3];
                pc[b] = p[5*b + 4];
                const float pcx = px[b] * invS, pcy = py[b] * invS;
                const float phw = 0.5f * pw[b], phh = 0.5f * ph[b];
                const float px0 = pcx - phw, px1 = pcx + phw;
                const float py0 = pcy - phh, py1 = pcy + phh;
                const float ltx = fmaxf(px0, tx0), lty = fmaxf(py0, ty0);
                const float rbx = fminf(px1, tx1), rby = fminf(py1, ty1);
                const float wi = fmaxf(rbx - ltx, 0.0f);
                const float hi = fmaxf(rby - lty, 0.0f);
                const float inter = wi * hi;
                const float area_p = pw[b] * ph[b];
                iou[b] = inter / (area_p + area_t - inter);
            }

            // argmax over 2 boxes; ties -> box 0 (matches jnp.argmax)
            const int b = (iou[1] > iou[0]) ? 1 : 0;
            const float max_iou = fmaxf(iou[0], iou[1]);

            const float dx = px[b] - t0x, dy = py[b] - t0y;
            const float lxy = dx*dx + dy*dy;
            const float dw = sqrtf(pw[b]) - sqrtf(t0w);
            const float dh = sqrtf(ph[b]) - sqrtf(t0h);
            const float lwh = dw*dw + dh*dh;
            const float dob = pc[b] - max_iou;
            const float lobj = dob * dob;
            const float lno = pc[0]*pc[0] + pc[1]*pc[1]; // tgt conf=0 when no obj

            float lcls = 0.0f;
            #pragma unroll
            for (int c = 0; c < 20; c++) {
                const float d = p[10 + c] - t[10 + c];
                lcls += d * d;
            }

            acc += of * (5.0f * (lxy + lwh) + lobj + lcls)
                 + (1.0f - of) * (0.5f * lno);
        }
        __syncwarp();   // all lanes done reading stage before it is reissued
    }

    acc *= (1.0f / (float)NBATCH);

    // warp reduce, then one atomic per block
    #pragma unroll
    for (int o = 16; o > 0; o >>= 1)
        acc += __shfl_down_sync(0xffffffffu, acc, o);
    if (lane == 0) wsum[wid] = acc;
    __syncthreads();
    if (threadIdx.x == 0) {
        float ssum = 0.0f;
        #pragma unroll
        for (int w = 0; w < NWARP; w++) ssum += wsum[w];
        atomicAdd(out, ssum);
    }
}

extern "C" void kernel_launch(void* const* d_in, const int* in_sizes, int n_in,
                              void* d_out, int out_size)
{
    const float* pred = (const float*)d_in[0];
    const float* tgt  = (const float*)d_in[1];
    float* out = (float*)d_out;

    cudaFuncSetAttribute(yolo_loss_kernel,
                         cudaFuncAttributeMaxDynamicSharedMemorySize, SMEM_DYN);

    yolo_zero_out<<<1, 32>>>(out);
    yolo_loss_kernel<<<GRID_N, BLOCK, SMEM_DYN>>>(pred, tgt, out);
}